// round 1
// baseline (speedup 1.0000x reference)
#include <cuda_runtime.h>

#define BB 64
#define CC 128
#define OO 128
#define HH 56
#define WW 56
#define HIDDEN 33
#define NK 4
#define HW_ 3136
#define CHW_ 401408
#define OUTIMG 25690112
#define WPERK 147456   // O*C*9

// ---- scratch (static device globals; no allocation) ----
__device__ float g_xq[(size_t)BB * CHW_];   // quantized input (real values)
__device__ float g_wq[NK * WPERK];          // quantized weights per expert
__device__ float g_pooled[BB * CC];
__device__ float g_a[BB];
__device__ float g_rqp[BB];
__device__ float g_attn[BB];
__device__ int   g_k[BB];

// ---------------------------------------------------------------------------
// 1) pooled[b][c] = mean over HxW
// ---------------------------------------------------------------------------
__global__ void pool_kernel(const float* __restrict__ x) {
    int bc = blockIdx.x;  // b*CC + c
    const float4* p = reinterpret_cast<const float4*>(x + (size_t)bc * HW_);
    float s = 0.f;
    for (int i = threadIdx.x; i < HW_ / 4; i += blockDim.x) {
        float4 v = p[i];
        s += (v.x + v.y) + (v.z + v.w);
    }
    for (int o = 16; o > 0; o >>= 1) s += __shfl_down_sync(0xffffffffu, s, o);
    __shared__ float red[4];
    int w = threadIdx.x >> 5, l = threadIdx.x & 31;
    if (l == 0) red[w] = s;
    __syncthreads();
    if (threadIdx.x == 0) {
        float t = (red[0] + red[1]) + (red[2] + red[3]);
        g_pooled[bc] = t * (1.0f / 3136.0f);
    }
}

// ---------------------------------------------------------------------------
// 2) gate: h = relu(pooled@fc1^T); raw = h@fc2^T + b; argmax; softmax;
//    attn_k = (1-s)+s ; rQp, a (grad_scale forward, rounding-order-faithful)
// ---------------------------------------------------------------------------
__global__ void gate_kernel(const float* __restrict__ fc1,
                            const float* __restrict__ fc2,
                            const float* __restrict__ fc2b,
                            const float* __restrict__ alpha_a,
                            float* __restrict__ raw_out) {
    int b = threadIdx.x;
    if (b >= BB) return;
    const float* pl = g_pooled + b * CC;
    float raw[NK];
#pragma unroll
    for (int k = 0; k < NK; ++k) raw[k] = fc2b[k];
    for (int j = 0; j < HIDDEN; ++j) {
        float h = 0.f;
        const float* f1 = fc1 + j * CC;
        for (int c = 0; c < CC; ++c) h = fmaf(pl[c], f1[c], h);
        h = fmaxf(h, 0.f);
#pragma unroll
        for (int k = 0; k < NK; ++k) raw[k] = fmaf(h, fc2[k * HIDDEN + j], raw[k]);
    }
    int kb = 0;
    float best = raw[0];
#pragma unroll
    for (int k = 1; k < NK; ++k)
        if (raw[k] > best) { best = raw[k]; kb = k; }
#pragma unroll
    for (int k = 0; k < NK; ++k) raw_out[b * NK + k] = raw[k];

    // softmax(raw / 34)
    float z[NK], m = -1e30f;
#pragma unroll
    for (int k = 0; k < NK; ++k) { z[k] = __fdiv_rn(raw[k], 34.0f); m = fmaxf(m, z[k]); }
    float sum = 0.f, ek = 0.f;
#pragma unroll
    for (int k = 0; k < NK; ++k) {
        float e = expf(z[k] - m);
        sum += e;
        if (k == kb) ek = e;
    }
    float s = __fdiv_rn(ek, sum);
    float attn = __fadd_rn(__fsub_rn(1.0f, s), s);   // forward value of STE one-hot
    float Qp = (float)((1 << (kb + 2)) - 1);         // 2^(k+2)-1
    float rqp = __fmul_rn(attn, Qp);
    float ralpha = __fmul_rn(attn, alpha_a[kb]);
    float g = __fdiv_rn(1.0f, sqrtf(__fmul_rn(401408.0f, rqp)));
    float t = __fmul_rn(ralpha, g);
    float a = __fadd_rn(__fsub_rn(ralpha, t), t);    // grad_scale forward
    g_a[b] = a;
    g_rqp[b] = rqp;
    g_attn[b] = attn;
    g_k[b] = kb;
}

// ---------------------------------------------------------------------------
// 3) xq = rint(clip(x/a, 0, rQp)) * a   (per-batch scalars)
// ---------------------------------------------------------------------------
__global__ void quantx_kernel(const float* __restrict__ x) {
    int b = blockIdx.y;
    size_t i = (size_t)b * CHW_ + (size_t)blockIdx.x * blockDim.x + threadIdx.x;
    float a = g_a[b], rqp = g_rqp[b];
    float v = __fdiv_rn(x[i], a);
    v = fminf(fmaxf(v, 0.0f), rqp);
    g_xq[i] = __fmul_rn(rintf(v), a);
}

// ---------------------------------------------------------------------------
// 4) wq = rint(clip(w/aw, Qn, Qp)) * aw  per expert k
// ---------------------------------------------------------------------------
__global__ void quantw_kernel(const float* __restrict__ w,
                              const float* __restrict__ alpha_w) {
    int k = blockIdx.y;
    int i = blockIdx.x * blockDim.x + threadIdx.x;
    float Qpw = (float)((1 << (k + 1)) - 1);
    float Qnw = -(float)(1 << (k + 1));
    float g = __fdiv_rn(1.0f, sqrtf(__fmul_rn(589824.0f, Qpw)));
    float aw = alpha_w[k];
    float t = __fmul_rn(aw, g);
    float awq = __fadd_rn(__fsub_rn(aw, t), t);      // grad_scale forward
    size_t idx = (size_t)k * WPERK + i;
    float v = __fdiv_rn(w[idx], awq);
    v = fminf(fmaxf(v, Qnw), Qpw);
    g_wq[idx] = __fmul_rn(rintf(v), awq);
}

// ---------------------------------------------------------------------------
// 5) direct conv 3x3 pad1: block = (b, 64 outputs, 4 rows x 56 cols)
//    256 threads; thread = 8 o x 7 pixels (56 accumulators)
// ---------------------------------------------------------------------------
__global__ __launch_bounds__(256) void conv_kernel(const float* __restrict__ bias,
                                                   float* __restrict__ out) {
    __shared__ float sx[8 * 6 * 58];   // 8 ch x 6 rows x 58 cols (padded)
    __shared__ float sw[8 * 64 * 9];   // 8 ch x 64 o x 9 taps
    const int b = blockIdx.z;
    const int o0 = blockIdx.y * 64;
    const int h0 = blockIdx.x * 4;
    const int k = g_k[b];
    const int tid = threadIdx.x;
    const int og = tid >> 5;           // warp id: output-channel group (uniform per warp)
    const int lane = tid & 31;

    int base[7], ooff[7];
#pragma unroll
    for (int j = 0; j < 7; ++j) {
        int p = lane + 32 * j;         // pixel 0..223 within the 4x56 tile
        int dh = p / 56, ww2 = p % 56;
        base[j] = dh * 58 + ww2;       // smem addr base (row offset handled by tap)
        ooff[j] = dh * 56 + ww2;       // output offset within tile
    }

    float acc[8][7];
#pragma unroll
    for (int i = 0; i < 8; ++i)
#pragma unroll
        for (int j = 0; j < 7; ++j) acc[i][j] = 0.f;

    const float* xq_b = g_xq + (size_t)b * CHW_;
    const float* wq_k = g_wq + (size_t)k * WPERK;

    for (int cc = 0; cc < CC; cc += 8) {
        // stage x: rows h0-1 .. h0+4, cols -1..56 (zero-padded)
#pragma unroll 1
        for (int i = tid; i < 2784; i += 256) {
            int c = i / 348, rem = i % 348;
            int row = rem / 58, col = rem % 58;
            int gr = h0 - 1 + row, gc = col - 1;
            float v = 0.f;
            if ((unsigned)gr < 56u && (unsigned)gc < 56u)
                v = xq_b[(cc + c) * HW_ + gr * 56 + gc];
            sx[i] = v;
        }
        // stage w
#pragma unroll 1
        for (int i = tid; i < 4608; i += 256) {
            int c = i / 576, rem = i % 576;
            int o = rem / 9, t = rem % 9;
            sw[i] = wq_k[(size_t)(o0 + o) * (CC * 9) + (cc + c) * 9 + t];
        }
        __syncthreads();

#pragma unroll 1
        for (int c = 0; c < 8; ++c) {
            const float* swc = sw + c * 576 + og * 72;
            const float* sxc = sx + c * 348;
#pragma unroll
            for (int t = 0; t < 9; ++t) {
                const int ro = (t / 3) * 58 + (t % 3);
                float wv[8];
#pragma unroll
                for (int i = 0; i < 8; ++i) wv[i] = swc[i * 9 + t];  // broadcast LDS
                float xv[7];
#pragma unroll
                for (int j = 0; j < 7; ++j) xv[j] = sxc[base[j] + ro];
#pragma unroll
                for (int i = 0; i < 8; ++i)
#pragma unroll
                    for (int j = 0; j < 7; ++j)
                        acc[i][j] = fmaf(wv[i], xv[j], acc[i][j]);
            }
        }
        __syncthreads();
    }

    const float attn = g_attn[b];
    float* outb = out + (size_t)b * (OO * HW_) + (size_t)h0 * 56;
#pragma unroll
    for (int i = 0; i < 8; ++i) {
        int o = o0 + og * 8 + i;
        float bb = __fmul_rn(attn, bias[k * OO + o]);
        float* outp = outb + (size_t)o * HW_;
#pragma unroll
        for (int j = 0; j < 7; ++j)
            outp[ooff[j]] = fmaf(attn, acc[i][j], bb);
    }
}

// ---------------------------------------------------------------------------
extern "C" void kernel_launch(void* const* d_in, const int* in_sizes, int n_in,
                              void* d_out, int out_size) {
    const float* x       = (const float*)d_in[0];
    const float* fc1     = (const float*)d_in[1];
    const float* fc2     = (const float*)d_in[2];
    const float* fc2b    = (const float*)d_in[3];
    const float* alpha_w = (const float*)d_in[4];
    const float* alpha_a = (const float*)d_in[5];
    const float* weight  = (const float*)d_in[6];
    const float* bias    = (const float*)d_in[7];
    float* out = (float*)d_out;

    pool_kernel<<<BB * CC, 128>>>(x);
    gate_kernel<<<1, 64>>>(fc1, fc2, fc2b, alpha_a, out + OUTIMG);
    quantx_kernel<<<dim3(1568, 64), 256>>>(x);
    quantw_kernel<<<dim3(576, NK), 256>>>(weight, alpha_w);
    conv_kernel<<<dim3(14, 2, 64), 256>>>(bias, out);
}

// round 2
// speedup vs baseline: 2.5592x; 2.5592x over previous
#include <cuda_runtime.h>

#define BB 64
#define CC 128
#define OO 128
#define HH 56
#define WW 56
#define HIDDEN 33
#define NK 4
#define HW_ 3136
#define CHW_ 401408
#define OUTIMG 25690112
#define C4 32          // C/4 packed channel groups

// ---- scratch (static device globals; no allocation) ----
__device__ unsigned int g_xq8[(size_t)BB * C4 * HW_];     // s8x4 packed qx [b][c4][p]
__device__ unsigned int g_wq8[NK * OO * C4 * 9];          // s8x4 packed qw [k][o][c4][t]
__device__ float g_pooled[BB * CC];
__device__ float g_a[BB];
__device__ float g_rqp[BB];
__device__ float g_attn[BB];
__device__ float g_awq[NK];
__device__ int   g_k[BB];

// ---------------------------------------------------------------------------
// 1) pooled[b][c] = mean over HxW
// ---------------------------------------------------------------------------
__global__ void pool_kernel(const float* __restrict__ x) {
    int bc = blockIdx.x;  // b*CC + c
    const float4* p = reinterpret_cast<const float4*>(x + (size_t)bc * HW_);
    float s = 0.f;
    for (int i = threadIdx.x; i < HW_ / 4; i += blockDim.x) {
        float4 v = p[i];
        s += (v.x + v.y) + (v.z + v.w);
    }
    for (int o = 16; o > 0; o >>= 1) s += __shfl_down_sync(0xffffffffu, s, o);
    __shared__ float red[4];
    int w = threadIdx.x >> 5, l = threadIdx.x & 31;
    if (l == 0) red[w] = s;
    __syncthreads();
    if (threadIdx.x == 0) {
        float t = (red[0] + red[1]) + (red[2] + red[3]);
        g_pooled[bc] = t * (1.0f / 3136.0f);
    }
}

// ---------------------------------------------------------------------------
// 2) gate: h = relu(pooled@fc1^T); raw = h@fc2^T + b; argmax; softmax;
//    attn_k = (1-s)+s ; rQp, a (grad_scale forward, rounding-order-faithful)
// ---------------------------------------------------------------------------
__global__ void gate_kernel(const float* __restrict__ fc1,
                            const float* __restrict__ fc2,
                            const float* __restrict__ fc2b,
                            const float* __restrict__ alpha_a,
                            float* __restrict__ raw_out) {
    int b = threadIdx.x;
    if (b >= BB) return;
    const float* pl = g_pooled + b * CC;
    float raw[NK];
#pragma unroll
    for (int k = 0; k < NK; ++k) raw[k] = fc2b[k];
    for (int j = 0; j < HIDDEN; ++j) {
        float h = 0.f;
        const float* f1 = fc1 + j * CC;
        for (int c = 0; c < CC; ++c) h = fmaf(pl[c], f1[c], h);
        h = fmaxf(h, 0.f);
#pragma unroll
        for (int k = 0; k < NK; ++k) raw[k] = fmaf(h, fc2[k * HIDDEN + j], raw[k]);
    }
    int kb = 0;
    float best = raw[0];
#pragma unroll
    for (int k = 1; k < NK; ++k)
        if (raw[k] > best) { best = raw[k]; kb = k; }
#pragma unroll
    for (int k = 0; k < NK; ++k) raw_out[b * NK + k] = raw[k];

    // softmax(raw / 34)
    float z[NK], m = -1e30f;
#pragma unroll
    for (int k = 0; k < NK; ++k) { z[k] = __fdiv_rn(raw[k], 34.0f); m = fmaxf(m, z[k]); }
    float sum = 0.f, ek = 0.f;
#pragma unroll
    for (int k = 0; k < NK; ++k) {
        float e = expf(z[k] - m);
        sum += e;
        if (k == kb) ek = e;
    }
    float s = __fdiv_rn(ek, sum);
    float attn = __fadd_rn(__fsub_rn(1.0f, s), s);   // forward value of STE one-hot
    float Qp = (float)((1 << (kb + 2)) - 1);         // 2^(k+2)-1
    float rqp = __fmul_rn(attn, Qp);
    float ralpha = __fmul_rn(attn, alpha_a[kb]);
    float g = __fdiv_rn(1.0f, sqrtf(__fmul_rn(401408.0f, rqp)));
    float t = __fmul_rn(ralpha, g);
    float a = __fadd_rn(__fsub_rn(ralpha, t), t);    // grad_scale forward
    g_a[b] = a;
    g_rqp[b] = rqp;
    g_attn[b] = attn;
    g_k[b] = kb;
}

// ---------------------------------------------------------------------------
// 3) qx = rint(clip(x/a, 0, rQp)) -> s8, pack 4 channels per u32
//    layout: g_xq8[((b*32 + c4)*HW_) + p]
// ---------------------------------------------------------------------------
__global__ void quantx_pack_kernel(const float* __restrict__ x) {
    int p = blockIdx.x * blockDim.x + threadIdx.x;
    if (p >= HW_) return;
    int c4 = blockIdx.y;
    int b  = blockIdx.z;
    float a = g_a[b], rqp = g_rqp[b];
    unsigned int pk = 0;
#pragma unroll
    for (int j = 0; j < 4; ++j) {
        float v = __fdiv_rn(x[((size_t)(b * CC + c4 * 4 + j)) * HW_ + p], a);
        v = fminf(fmaxf(v, 0.0f), rqp);
        unsigned int q = (unsigned int)__float2int_rn(v);   // 0..31
        pk |= q << (8 * j);
    }
    g_xq8[((size_t)(b * C4 + c4)) * HW_ + p] = pk;
}

// ---------------------------------------------------------------------------
// 4) qw = rint(clip(w/awq, Qn, Qp)) -> s8, pack 4 channels per u32
//    layout: g_wq8[(((k*OO + o)*C4) + c4)*9 + t]
// ---------------------------------------------------------------------------
__global__ void quantw_pack_kernel(const float* __restrict__ w,
                                   const float* __restrict__ alpha_w) {
    int k = blockIdx.y;
    int i = blockIdx.x * blockDim.x + threadIdx.x;   // over OO*C4*9 = 36864
    float Qpw = (float)((1 << (k + 1)) - 1);
    float Qnw = -(float)(1 << (k + 1));
    float g = __fdiv_rn(1.0f, sqrtf(__fmul_rn(589824.0f, Qpw)));
    float aw = alpha_w[k];
    float t = __fmul_rn(aw, g);
    float awq = __fadd_rn(__fsub_rn(aw, t), t);      // grad_scale forward
    if (i == 0) g_awq[k] = awq;

    int o  = i / (C4 * 9);
    int r  = i % (C4 * 9);
    int c4 = r / 9;
    int tt = r % 9;
    unsigned int pk = 0;
#pragma unroll
    for (int j = 0; j < 4; ++j) {
        size_t idx = ((size_t)(k * OO + o) * CC + (c4 * 4 + j)) * 9 + tt;
        float v = __fdiv_rn(w[idx], awq);
        v = fminf(fmaxf(v, Qnw), Qpw);
        int q = __float2int_rn(v);                   // -32..31
        pk |= ((unsigned int)q & 0xffu) << (8 * j);
    }
    g_wq8[((size_t)(k * OO + o) * C4 + c4) * 9 + tt] = pk;
}

// ---------------------------------------------------------------------------
// 5) direct conv 3x3 pad1 with dp4a: block = (b, 64 outputs, 4 rows x 56 cols)
//    256 threads; thread = 8 o x 7 pixels (56 int accumulators)
//    4 MACs per dp4a -> inner loop is 4x shorter than the FFMA version
// ---------------------------------------------------------------------------
__global__ __launch_bounds__(256) void conv_kernel(const float* __restrict__ bias,
                                                   float* __restrict__ out) {
    __shared__ unsigned int sx[8 * 6 * 58];   // 8 c4 x 6 rows x 58 cols (padded)
    __shared__ unsigned int sw[8 * 64 * 9];   // 8 c4 x 64 o x 9 taps
    const int b = blockIdx.z;
    const int o0 = blockIdx.y * 64;
    const int h0 = blockIdx.x * 4;
    const int k = g_k[b];
    const int tid = threadIdx.x;
    const int og = tid >> 5;           // warp id: output-channel group (uniform per warp)
    const int lane = tid & 31;

    int base[7], ooff[7];
#pragma unroll
    for (int j = 0; j < 7; ++j) {
        int p = lane + 32 * j;         // pixel 0..223 within the 4x56 tile
        int dh = p / 56, ww2 = p % 56;
        base[j] = dh * 58 + ww2;
        ooff[j] = dh * 56 + ww2;
    }

    int acc[8][7];
#pragma unroll
    for (int i = 0; i < 8; ++i)
#pragma unroll
        for (int j = 0; j < 7; ++j) acc[i][j] = 0;

    const unsigned int* xq_b = g_xq8 + (size_t)b * (C4 * HW_);
    const unsigned int* wq_k = g_wq8 + (size_t)k * (OO * C4 * 9);

    for (int cc = 0; cc < C4; cc += 8) {
        // stage x: 8 c4-groups, rows h0-1 .. h0+4, cols -1..56 (zero-padded)
#pragma unroll 1
        for (int i = tid; i < 2784; i += 256) {
            int c = i / 348, rem = i % 348;
            int row = rem / 58, col = rem % 58;
            int gr = h0 - 1 + row, gc = col - 1;
            unsigned int v = 0;
            if ((unsigned)gr < 56u && (unsigned)gc < 56u)
                v = xq_b[(size_t)(cc + c) * HW_ + gr * 56 + gc];
            sx[i] = v;
        }
        // stage w
#pragma unroll 1
        for (int i = tid; i < 4608; i += 256) {
            int c = i / 576, rem = i % 576;
            int o = rem / 9, t = rem % 9;
            sw[i] = wq_k[((size_t)(o0 + o) * C4 + (cc + c)) * 9 + t];
        }
        __syncthreads();

#pragma unroll 1
        for (int c = 0; c < 8; ++c) {
            const unsigned int* swc = sw + c * 576 + og * 72;
            const unsigned int* sxc = sx + c * 348;
#pragma unroll
            for (int t = 0; t < 9; ++t) {
                const int ro = (t / 3) * 58 + (t % 3);
                int wv[8];
#pragma unroll
                for (int i = 0; i < 8; ++i) wv[i] = (int)swc[i * 9 + t];  // broadcast LDS
                int xv[7];
#pragma unroll
                for (int j = 0; j < 7; ++j) xv[j] = (int)sxc[base[j] + ro];
#pragma unroll
                for (int i = 0; i < 8; ++i)
#pragma unroll
                    for (int j = 0; j < 7; ++j)
                        acc[i][j] = __dp4a(wv[i], xv[j], acc[i][j]);
            }
        }
        __syncthreads();
    }

    const float attn = g_attn[b];
    const float scale = __fmul_rn(attn, __fmul_rn(g_a[b], g_awq[k]));
    float* outb = out + (size_t)b * (OO * HW_) + (size_t)h0 * 56;
#pragma unroll
    for (int i = 0; i < 8; ++i) {
        int o = o0 + og * 8 + i;
        float bb = __fmul_rn(attn, bias[k * OO + o]);
        float* outp = outb + (size_t)o * HW_;
#pragma unroll
        for (int j = 0; j < 7; ++j)
            outp[ooff[j]] = fmaf(scale, (float)acc[i][j], bb);
    }
}

// ---------------------------------------------------------------------------
extern "C" void kernel_launch(void* const* d_in, const int* in_sizes, int n_in,
                              void* d_out, int out_size) {
    const float* x       = (const float*)d_in[0];
    const float* fc1     = (const float*)d_in[1];
    const float* fc2     = (const float*)d_in[2];
    const float* fc2b    = (const float*)d_in[3];
    const float* alpha_w = (const float*)d_in[4];
    const float* alpha_a = (const float*)d_in[5];
    const float* weight  = (const float*)d_in[6];
    const float* bias    = (const float*)d_in[7];
    float* out = (float*)d_out;

    pool_kernel<<<BB * CC, 128>>>(x);
    gate_kernel<<<1, 64>>>(fc1, fc2, fc2b, alpha_a, out + OUTIMG);
    quantw_pack_kernel<<<dim3(144, NK), 256>>>(weight, alpha_w);
    quantx_pack_kernel<<<dim3(13, C4, BB), 256>>>(x);
    conv_kernel<<<dim3(14, 2, 64), 256>>>(bias, out);
}

// round 4
// speedup vs baseline: 2.7284x; 1.0661x over previous
#include <cuda_runtime.h>
#include <cstdint>

#define BB 64
#define CC 128
#define OO 128
#define HIDDEN 33
#define NK 4
#define HW_ 3136
#define OUTIMG 25690112
#define XPAD 33

// padded NHWC s8 x: [b][58][58][128]  (rows/cols -1..56 zero-padded), viewed as u32
__device__ __align__(16) unsigned int g_x8[(size_t)BB * 58 * 58 * 32];
// packed s8 weights: [k][tap][o][c4] u32
__device__ __align__(16) unsigned int g_w8[NK * 9 * OO * 32];
__device__ float g_pooled[BB * CC];
__device__ float g_a[BB];
__device__ float g_rqp[BB];
__device__ float g_attn[BB];
__device__ float g_awq[NK];
__device__ int   g_k[BB];

// ---------------------------------------------------------------------------
// 1) pooled[b][c] = mean over HxW
// ---------------------------------------------------------------------------
__global__ void pool_kernel(const float* __restrict__ x) {
    int bc = blockIdx.x;
    const float4* p = reinterpret_cast<const float4*>(x + (size_t)bc * HW_);
    float s = 0.f;
    for (int i = threadIdx.x; i < HW_ / 4; i += blockDim.x) {
        float4 v = p[i];
        s += (v.x + v.y) + (v.z + v.w);
    }
    for (int o = 16; o > 0; o >>= 1) s += __shfl_down_sync(0xffffffffu, s, o);
    __shared__ float red[4];
    int w = threadIdx.x >> 5, l = threadIdx.x & 31;
    if (l == 0) red[w] = s;
    __syncthreads();
    if (threadIdx.x == 0)
        g_pooled[bc] = ((red[0] + red[1]) + (red[2] + red[3])) * (1.0f / 3136.0f);
}

// ---------------------------------------------------------------------------
// 2) gate (per-batch scalars; STE/grad_scale forward, rounding-order faithful)
// ---------------------------------------------------------------------------
__global__ void gate_kernel(const float* __restrict__ fc1,
                            const float* __restrict__ fc2,
                            const float* __restrict__ fc2b,
                            const float* __restrict__ alpha_a,
                            float* __restrict__ raw_out) {
    int b = threadIdx.x;
    if (b >= BB) return;
    const float* pl = g_pooled + b * CC;
    float raw[NK];
#pragma unroll
    for (int k = 0; k < NK; ++k) raw[k] = fc2b[k];
    for (int j = 0; j < HIDDEN; ++j) {
        float h = 0.f;
        const float* f1 = fc1 + j * CC;
        for (int c = 0; c < CC; ++c) h = fmaf(pl[c], f1[c], h);
        h = fmaxf(h, 0.f);
#pragma unroll
        for (int k = 0; k < NK; ++k) raw[k] = fmaf(h, fc2[k * HIDDEN + j], raw[k]);
    }
    int kb = 0;
    float best = raw[0];
#pragma unroll
    for (int k = 1; k < NK; ++k)
        if (raw[k] > best) { best = raw[k]; kb = k; }
#pragma unroll
    for (int k = 0; k < NK; ++k) raw_out[b * NK + k] = raw[k];

    float z[NK], m = -1e30f;
#pragma unroll
    for (int k = 0; k < NK; ++k) { z[k] = __fdiv_rn(raw[k], 34.0f); m = fmaxf(m, z[k]); }
    float sum = 0.f, ek = 0.f;
#pragma unroll
    for (int k = 0; k < NK; ++k) {
        float e = expf(z[k] - m);
        sum += e;
        if (k == kb) ek = e;
    }
    float s = __fdiv_rn(ek, sum);
    float attn = __fadd_rn(__fsub_rn(1.0f, s), s);
    float Qp = (float)((1 << (kb + 2)) - 1);
    float rqp = __fmul_rn(attn, Qp);
    float ralpha = __fmul_rn(attn, alpha_a[kb]);
    float g = __fdiv_rn(1.0f, sqrtf(__fmul_rn(401408.0f, rqp)));
    float t = __fmul_rn(ralpha, g);
    float a = __fadd_rn(__fsub_rn(ralpha, t), t);
    g_a[b] = a;
    g_rqp[b] = rqp;
    g_attn[b] = attn;
    g_k[b] = kb;
}

// ---------------------------------------------------------------------------
// 3) x -> padded NHWC s8 (quantized codes): g_x8[b][prow][pcol][c4]
// ---------------------------------------------------------------------------
__global__ void xform_kernel(const float* __restrict__ x) {
    __shared__ unsigned int s[56 * 32];    // [w][c4] packed row
    int b = blockIdx.z, prow = blockIdx.y;
    int tid = threadIdx.x;
    unsigned int* dst = g_x8 + ((size_t)(b * 58 + prow) * 58) * 32;
    if (prow == 0 || prow == 57) {
        for (int i = tid; i < 58 * 32; i += 256) dst[i] = 0;
        return;
    }
    int h = prow - 1;
    float a = g_a[b], rqp = g_rqp[b];
    unsigned char* s8 = reinterpret_cast<unsigned char*>(s);
    for (int i = tid; i < 7168; i += 256) {
        int c = i / 56, w = i % 56;
        float v = __fdiv_rn(x[((size_t)(b * CC + c)) * HW_ + h * 56 + w], a);
        v = fminf(fmaxf(v, 0.0f), rqp);
        s8[w * 128 + c] = (unsigned char)__float2int_rn(v);   // 0..31
    }
    __syncthreads();
    for (int i = tid; i < 58 * 32; i += 256) {
        int pcol = i >> 5, c4 = i & 31;
        unsigned int v = 0;
        if (pcol >= 1 && pcol <= 56) v = s[(pcol - 1) * 32 + c4];
        dst[i] = v;
    }
}

// ---------------------------------------------------------------------------
// 4) w -> packed s8: g_w8[k][tap][o][c4]
// ---------------------------------------------------------------------------
__global__ void wform_kernel(const float* __restrict__ w,
                             const float* __restrict__ alpha_w) {
    int k = blockIdx.y;
    int i = blockIdx.x * blockDim.x + threadIdx.x;   // over 128*32*9 = 36864
    float Qpw = (float)((1 << (k + 1)) - 1);
    float Qnw = -(float)(1 << (k + 1));
    float g = __fdiv_rn(1.0f, sqrtf(__fmul_rn(589824.0f, Qpw)));
    float aw = alpha_w[k];
    float t = __fmul_rn(aw, g);
    float awq = __fadd_rn(__fsub_rn(aw, t), t);
    if (i == 0) g_awq[k] = awq;
    int o   = i / 288;
    int r   = i % 288;
    int c4  = r / 9;
    int tap = r % 9;
    unsigned int pk = 0;
#pragma unroll
    for (int j = 0; j < 4; ++j) {
        size_t idx = ((size_t)(k * OO + o) * CC + c4 * 4 + j) * 9 + tap;
        float v = __fdiv_rn(w[idx], awq);
        v = fminf(fmaxf(v, Qnw), Qpw);
        int q = __float2int_rn(v);                  // -32..31
        pk |= ((unsigned int)q & 0xffu) << (8 * j);
    }
    g_w8[((size_t)(k * 9 + tap) * OO + o) * 32 + c4] = pk;
}

// ---------------------------------------------------------------------------
// 5) conv via IMMA mma.sync m16n8k32 s8: block = (b, 2 rows -> 112 px, 128 o)
//    8 warps: warp = 32 o x 56 px = 2 m-frags x 7 n-frags
// ---------------------------------------------------------------------------
__device__ __forceinline__ void imma(int& c0, int& c1, int& c2, int& c3,
                                     unsigned a0, unsigned a1, unsigned a2, unsigned a3,
                                     unsigned b0, unsigned b1) {
    asm volatile("mma.sync.aligned.m16n8k32.row.col.s32.s8.s8.s32 "
                 "{%0,%1,%2,%3}, {%4,%5,%6,%7}, {%8,%9}, {%0,%1,%2,%3};"
                 : "+r"(c0), "+r"(c1), "+r"(c2), "+r"(c3)
                 : "r"(a0), "r"(a1), "r"(a2), "r"(a3), "r"(b0), "r"(b1));
}

__global__ __launch_bounds__(256) void conv_kernel(const float* __restrict__ bias,
                                                   float* __restrict__ out) {
    __shared__ unsigned int sx[112 * XPAD];   // [px][c4] pad-33
    __shared__ unsigned int sw[128 * XPAD];   // [o][c4] pad-33
    const int tid = threadIdx.x;
    const int b = blockIdx.y;
    const int h0 = blockIdx.x * 2;
    const int k = g_k[b];
    const int wid = tid >> 5, lane = tid & 31;
    const int gid = lane >> 2, tig = lane & 3;
    const int o0w = (wid & 3) * 32;       // warp o base
    const int px0 = (wid >> 2) * 56;      // warp px base

    int acc[2][7][4];
#pragma unroll
    for (int mf = 0; mf < 2; ++mf)
#pragma unroll
        for (int nf = 0; nf < 7; ++nf)
#pragma unroll
            for (int r = 0; r < 4; ++r) acc[mf][nf][r] = 0;

    const unsigned int* wkp = g_w8 + (size_t)k * 9 * OO * 32;

    for (int tap = 0; tap < 9; ++tap) {
        __syncthreads();
        // stage W: 128 o x 32 u32
        const unsigned int* wsrc = wkp + (size_t)tap * OO * 32;
#pragma unroll 1
        for (int i = tid; i < 4096; i += 256) {
            int o = i >> 5, c4 = i & 31;
            sw[o * XPAD + c4] = wsrc[i];
        }
        // stage X: 112 px x 32 u32 from padded buffer (contiguous per row)
        const int dh = tap / 3, dw = tap % 3;
        const unsigned int* xsrc = g_x8 + ((size_t)(b * 58 + h0 + dh) * 58 + dw) * 32;
#pragma unroll 1
        for (int i = tid; i < 3584; i += 256) {
            int px = i >> 5, c4 = i & 31;
            int r = px / 56, w2 = px % 56;
            sx[px * XPAD + c4] = xsrc[(size_t)(r * 58 + w2) * 32 + c4];
        }
        __syncthreads();

#pragma unroll
        for (int ks = 0; ks < 4; ++ks) {
            const int kb8 = ks * 8;
            unsigned a[2][4];
#pragma unroll
            for (int mf = 0; mf < 2; ++mf) {
                int row = o0w + mf * 16 + gid;
                a[mf][0] = sw[row * XPAD + kb8 + tig];
                a[mf][1] = sw[(row + 8) * XPAD + kb8 + tig];
                a[mf][2] = sw[row * XPAD + kb8 + tig + 4];
                a[mf][3] = sw[(row + 8) * XPAD + kb8 + tig + 4];
            }
#pragma unroll
            for (int nf = 0; nf < 7; ++nf) {
                int col = px0 + nf * 8 + gid;
                unsigned b0 = sx[col * XPAD + kb8 + tig];
                unsigned b1 = sx[col * XPAD + kb8 + tig + 4];
#pragma unroll
                for (int mf = 0; mf < 2; ++mf)
                    imma(acc[mf][nf][0], acc[mf][nf][1], acc[mf][nf][2], acc[mf][nf][3],
                         a[mf][0], a[mf][1], a[mf][2], a[mf][3], b0, b1);
            }
        }
    }

    // epilogue
    const float attn = g_attn[b];
    const float scale = __fmul_rn(attn, __fmul_rn(g_a[b], g_awq[k]));
#pragma unroll
    for (int mf = 0; mf < 2; ++mf) {
#pragma unroll
        for (int half = 0; half < 2; ++half) {
            int o = o0w + mf * 16 + gid + half * 8;
            float bb = __fmul_rn(attn, bias[k * OO + o]);
            float* po = out + (size_t)(b * OO + o) * HW_ + h0 * 56 + px0 + tig * 2;
#pragma unroll
            for (int nf = 0; nf < 7; ++nf) {
                float2 v;
                v.x = fmaf(scale, (float)acc[mf][nf][half * 2 + 0], bb);
                v.y = fmaf(scale, (float)acc[mf][nf][half * 2 + 1], bb);
                *reinterpret_cast<float2*>(po + nf * 8) = v;
            }
        }
    }
}

// ---------------------------------------------------------------------------
extern "C" void kernel_launch(void* const* d_in, const int* in_sizes, int n_in,
                              void* d_out, int out_size) {
    const float* x       = (const float*)d_in[0];
    const float* fc1     = (const float*)d_in[1];
    const float* fc2     = (const float*)d_in[2];
    const float* fc2b    = (const float*)d_in[3];
    const float* alpha_w = (const float*)d_in[4];
    const float* alpha_a = (const float*)d_in[5];
    const float* weight  = (const float*)d_in[6];
    const float* bias    = (const float*)d_in[7];
    float* out = (float*)d_out;

    pool_kernel<<<BB * CC, 128>>>(x);
    gate_kernel<<<1, 64>>>(fc1, fc2, fc2b, alpha_a, out + OUTIMG);
    wform_kernel<<<dim3(144, NK), 256>>>(weight, alpha_w);
    xform_kernel<<<dim3(1, 58, BB), 256>>>(x);
    conv_kernel<<<dim3(28, BB), 256>>>(bias, out);
}

// round 5
// speedup vs baseline: 3.2092x; 1.1762x over previous
#include <cuda_runtime.h>
#include <cstdint>

#define BB 64
#define CC 128
#define OO 128
#define HIDDEN 33
#define NK 4
#define HW_ 3136
#define OUTIMG 25690112
#define XP 36                    // smem pitch in words (conflict-free: 36 mod 32 = 4)

// padded NHWC s8 x: [b][58][58][128], viewed as u32[b][58][58][32]
__device__ __align__(16) unsigned int g_x8[(size_t)BB * 58 * 58 * 32];
// packed s8 weights: [k][tap][o][c4] u32
__device__ __align__(16) unsigned int g_w8[NK * 9 * OO * 32];
__device__ float g_pooled[BB * CC];
__device__ float g_a[BB];
__device__ float g_rqp[BB];
__device__ float g_attn[BB];
__device__ float g_awq[NK];
__device__ int   g_k[BB];

__device__ __forceinline__ uint32_t smem_u32(const void* p) {
    uint32_t a;
    asm("{ .reg .u64 t; cvta.to.shared.u64 t, %1; cvt.u32.u64 %0, t; }" : "=r"(a) : "l"(p));
    return a;
}

// ---------------------------------------------------------------------------
// 1) pooled[b][c] = mean over HxW
// ---------------------------------------------------------------------------
__global__ void pool_kernel(const float* __restrict__ x) {
    int bc = blockIdx.x;
    const float4* p = reinterpret_cast<const float4*>(x + (size_t)bc * HW_);
    float s = 0.f;
    for (int i = threadIdx.x; i < HW_ / 4; i += blockDim.x) {
        float4 v = p[i];
        s += (v.x + v.y) + (v.z + v.w);
    }
    for (int o = 16; o > 0; o >>= 1) s += __shfl_down_sync(0xffffffffu, s, o);
    __shared__ float red[4];
    int w = threadIdx.x >> 5, l = threadIdx.x & 31;
    if (l == 0) red[w] = s;
    __syncthreads();
    if (threadIdx.x == 0)
        g_pooled[bc] = ((red[0] + red[1]) + (red[2] + red[3])) * (1.0f / 3136.0f);
}

// ---------------------------------------------------------------------------
// 2) gate (per-batch scalars; STE/grad_scale forward, rounding-order faithful)
// ---------------------------------------------------------------------------
__global__ void gate_kernel(const float* __restrict__ fc1,
                            const float* __restrict__ fc2,
                            const float* __restrict__ fc2b,
                            const float* __restrict__ alpha_a,
                            float* __restrict__ raw_out) {
    int b = threadIdx.x;
    if (b >= BB) return;
    const float* pl = g_pooled + b * CC;
    float raw[NK];
#pragma unroll
    for (int k = 0; k < NK; ++k) raw[k] = fc2b[k];
    for (int j = 0; j < HIDDEN; ++j) {
        float h = 0.f;
        const float* f1 = fc1 + j * CC;
        for (int c = 0; c < CC; ++c) h = fmaf(pl[c], f1[c], h);
        h = fmaxf(h, 0.f);
#pragma unroll
        for (int k = 0; k < NK; ++k) raw[k] = fmaf(h, fc2[k * HIDDEN + j], raw[k]);
    }
    int kb = 0;
    float best = raw[0];
#pragma unroll
    for (int k = 1; k < NK; ++k)
        if (raw[k] > best) { best = raw[k]; kb = k; }
#pragma unroll
    for (int k = 0; k < NK; ++k) raw_out[b * NK + k] = raw[k];

    float z[NK], m = -1e30f;
#pragma unroll
    for (int k = 0; k < NK; ++k) { z[k] = __fdiv_rn(raw[k], 34.0f); m = fmaxf(m, z[k]); }
    float sum = 0.f, ek = 0.f;
#pragma unroll
    for (int k = 0; k < NK; ++k) {
        float e = expf(z[k] - m);
        sum += e;
        if (k == kb) ek = e;
    }
    float s = __fdiv_rn(ek, sum);
    float attn = __fadd_rn(__fsub_rn(1.0f, s), s);
    float Qp = (float)((1 << (kb + 2)) - 1);
    float rqp = __fmul_rn(attn, Qp);
    float ralpha = __fmul_rn(attn, alpha_a[kb]);
    float g = __fdiv_rn(1.0f, sqrtf(__fmul_rn(401408.0f, rqp)));
    float t = __fmul_rn(ralpha, g);
    float a = __fadd_rn(__fsub_rn(ralpha, t), t);
    g_a[b] = a;
    g_rqp[b] = rqp;
    g_attn[b] = attn;
    g_k[b] = kb;
}

// ---------------------------------------------------------------------------
// 3) x -> padded NHWC s8: g_x8[b][prow][pcol][c4]  (conflict-free pitch 132B)
// ---------------------------------------------------------------------------
__global__ void xform_kernel(const float* __restrict__ x) {
    __shared__ unsigned int s[56 * 33];    // [w][c4] packed row, pitch 33 words
    int b = blockIdx.z, prow = blockIdx.y;
    int tid = threadIdx.x;
    unsigned int* dst = g_x8 + ((size_t)(b * 58 + prow) * 58) * 32;
    if (prow == 0 || prow == 57) {
        for (int i = tid; i < 58 * 32; i += 256) dst[i] = 0;
        return;
    }
    int h = prow - 1;
    float a = g_a[b], rqp = g_rqp[b];
    unsigned char* s8 = reinterpret_cast<unsigned char*>(s);
    for (int i = tid; i < 7168; i += 256) {
        int c = i / 56, w = i % 56;
        float v = __fdiv_rn(x[((size_t)(b * CC + c)) * HW_ + h * 56 + w], a);
        v = fminf(fmaxf(v, 0.0f), rqp);
        s8[w * 132 + c] = (unsigned char)__float2int_rn(v);   // 0..31
    }
    __syncthreads();
    for (int i = tid; i < 58 * 32; i += 256) {
        int pcol = i >> 5, c4 = i & 31;
        unsigned int v = 0;
        if (pcol >= 1 && pcol <= 56) v = s[(pcol - 1) * 33 + c4];
        dst[i] = v;
    }
}

// ---------------------------------------------------------------------------
// 4) w -> packed s8: g_w8[k][tap][o][c4]
// ---------------------------------------------------------------------------
__global__ void wform_kernel(const float* __restrict__ w,
                             const float* __restrict__ alpha_w) {
    int k = blockIdx.y;
    int i = blockIdx.x * blockDim.x + threadIdx.x;   // over 128*32*9 = 36864
    float Qpw = (float)((1 << (k + 1)) - 1);
    float Qnw = -(float)(1 << (k + 1));
    float g = __fdiv_rn(1.0f, sqrtf(__fmul_rn(589824.0f, Qpw)));
    float aw = alpha_w[k];
    float t = __fmul_rn(aw, g);
    float awq = __fadd_rn(__fsub_rn(aw, t), t);
    if (i == 0) g_awq[k] = awq;
    int o   = i / 288;
    int r   = i % 288;
    int c4  = r / 9;
    int tap = r % 9;
    unsigned int pk = 0;
#pragma unroll
    for (int j = 0; j < 4; ++j) {
        size_t idx = ((size_t)(k * OO + o) * CC + c4 * 4 + j) * 9 + tap;
        float v = __fdiv_rn(w[idx], awq);
        v = fminf(fmaxf(v, Qnw), Qpw);
        int q = __float2int_rn(v);
        pk |= ((unsigned int)q & 0xffu) << (8 * j);
    }
    g_w8[((size_t)(k * 9 + tap) * OO + o) * 32 + c4] = pk;
}

// ---------------------------------------------------------------------------
// 5) conv via IMMA, cp.async double-buffered, ldmatrix frags
//    block = (b, 2 rows -> 112 px, 128 o); 8 warps, warp = 32 o x 56 px
// ---------------------------------------------------------------------------
#define XW (112 * XP)        // 4032 words per X buffer
#define WW_ (128 * XP)       // 4608 words per W buffer
#define SMEM_WORDS (2 * XW + 2 * WW_)   // 17280 words = 69120 B

__device__ __forceinline__ void imma(int& c0, int& c1, int& c2, int& c3,
                                     unsigned a0, unsigned a1, unsigned a2, unsigned a3,
                                     unsigned b0, unsigned b1) {
    asm volatile("mma.sync.aligned.m16n8k32.row.col.s32.s8.s8.s32 "
                 "{%0,%1,%2,%3}, {%4,%5,%6,%7}, {%8,%9}, {%0,%1,%2,%3};"
                 : "+r"(c0), "+r"(c1), "+r"(c2), "+r"(c3)
                 : "r"(a0), "r"(a1), "r"(a2), "r"(a3), "r"(b0), "r"(b1));
}
__device__ __forceinline__ void cp16(uint32_t daddr, const void* src) {
    asm volatile("cp.async.cg.shared.global [%0], [%1], 16;" :: "r"(daddr), "l"(src) : "memory");
}

__global__ __launch_bounds__(256) void conv_kernel(const float* __restrict__ bias,
                                                   float* __restrict__ out) {
    extern __shared__ __align__(16) unsigned int smem[];
    const uint32_t sbase = smem_u32(smem);
    const int tid = threadIdx.x;
    const int b = blockIdx.y;
    const int h0 = blockIdx.x * 2;
    const int k = g_k[b];
    const int wid = tid >> 5, lane = tid & 31;
    const int gid = lane >> 2, tig = lane & 3;
    const int o0w = (wid & 3) * 32;       // warp o base
    const int px0 = (wid >> 2) * 56;      // warp px base

    // ldmatrix lane address components
    const int a_row = ((lane >> 3) & 1) * 8 + (lane & 7);   // A .x4 tile row
    const int a_kh4 = (lane >> 4) * 4;                      // A k-half word offset
    const int b_col = lane & 7;                             // B .x2 tile col
    const int b_kh4 = ((lane >> 3) & 1) * 4;

    int acc[2][7][4];
#pragma unroll
    for (int mf = 0; mf < 2; ++mf)
#pragma unroll
        for (int nf = 0; nf < 7; ++nf)
#pragma unroll
            for (int r = 0; r < 4; ++r) acc[mf][nf][r] = 0;

    const unsigned int* wkp = g_w8 + (size_t)k * 9 * OO * 32;
    const unsigned int* xbp = g_x8 + (size_t)(b * 58 + h0) * 58 * 32;

    // stage tap into buffer bs
    auto stage = [&](int tap, int bs) {
        const unsigned int* wsrc = wkp + (size_t)tap * OO * 32;
        const int dh = tap / 3, dw = tap % 3;
        const unsigned int* xsrc = xbp + (size_t)(dh * 58 + dw) * 32;
        const uint32_t swd = sbase + (2 * XW + bs * WW_) * 4;
        const uint32_t sxd = sbase + (bs * XW) * 4;
#pragma unroll
        for (int t = 0; t < 4; ++t) {
            int i = tid + t * 256;            // 1024 W chunks
            int o = i >> 3, j = i & 7;
            cp16(swd + (o * XP + j * 4) * 4, wsrc + o * 32 + j * 4);
        }
#pragma unroll
        for (int t = 0; t < 4; ++t) {
            int i = tid + t * 256;            // 896 X chunks
            if (i < 896) {
                int px = i >> 3, j = i & 7;
                int r = px / 56, w2 = px % 56;
                cp16(sxd + (px * XP + j * 4) * 4, xsrc + (r * 58 + w2) * 32 + j * 4);
            }
        }
    };

    stage(0, 0);
    asm volatile("cp.async.commit_group;" ::: "memory");

    for (int tap = 0; tap < 9; ++tap) {
        const int bs = tap & 1;
        if (tap + 1 < 9) {
            stage(tap + 1, bs ^ 1);
            asm volatile("cp.async.commit_group;" ::: "memory");
            asm volatile("cp.async.wait_group 1;" ::: "memory");
        } else {
            asm volatile("cp.async.wait_group 0;" ::: "memory");
        }
        __syncthreads();

        const uint32_t sww = sbase + (2 * XW + bs * WW_) * 4;
        const uint32_t sxw = sbase + (bs * XW) * 4;
#pragma unroll
        for (int ks = 0; ks < 4; ++ks) {
            const int kb8 = ks * 8;
            unsigned a[2][4];
#pragma unroll
            for (int mf = 0; mf < 2; ++mf) {
                uint32_t ad = sww + ((o0w + mf * 16 + a_row) * XP + kb8 + a_kh4) * 4;
                asm volatile("ldmatrix.sync.aligned.m8n8.x4.b16 {%0,%1,%2,%3}, [%4];"
                             : "=r"(a[mf][0]), "=r"(a[mf][1]), "=r"(a[mf][2]), "=r"(a[mf][3])
                             : "r"(ad));
            }
#pragma unroll
            for (int nf = 0; nf < 7; ++nf) {
                uint32_t bd = sxw + ((px0 + nf * 8 + b_col) * XP + kb8 + b_kh4) * 4;
                unsigned b0, b1;
                asm volatile("ldmatrix.sync.aligned.m8n8.x2.b16 {%0,%1}, [%2];"
                             : "=r"(b0), "=r"(b1) : "r"(bd));
#pragma unroll
                for (int mf = 0; mf < 2; ++mf)
                    imma(acc[mf][nf][0], acc[mf][nf][1], acc[mf][nf][2], acc[mf][nf][3],
                         a[mf][0], a[mf][1], a[mf][2], a[mf][3], b0, b1);
            }
        }
        __syncthreads();
    }

    // epilogue
    const float attn = g_attn[b];
    const float scale = __fmul_rn(attn, __fmul_rn(g_a[b], g_awq[k]));
#pragma unroll
    for (int mf = 0; mf < 2; ++mf) {
#pragma unroll
        for (int half = 0; half < 2; ++half) {
            int o = o0w + mf * 16 + gid + half * 8;
            float bb = __fmul_rn(attn, bias[k * OO + o]);
            float* po = out + (size_t)(b * OO + o) * HW_ + h0 * 56 + px0 + tig * 2;
#pragma unroll
            for (int nf = 0; nf < 7; ++nf) {
                float2 v;
                v.x = fmaf(scale, (float)acc[mf][nf][half * 2 + 0], bb);
                v.y = fmaf(scale, (float)acc[mf][nf][half * 2 + 1], bb);
                *reinterpret_cast<float2*>(po + nf * 8) = v;
            }
        }
    }
}

// ---------------------------------------------------------------------------
extern "C" void kernel_launch(void* const* d_in, const int* in_sizes, int n_in,
                              void* d_out, int out_size) {
    const float* x       = (const float*)d_in[0];
    const float* fc1     = (const float*)d_in[1];
    const float* fc2     = (const float*)d_in[2];
    const float* fc2b    = (const float*)d_in[3];
    const float* alpha_w = (const float*)d_in[4];
    const float* alpha_a = (const float*)d_in[5];
    const float* weight  = (const float*)d_in[6];
    const float* bias    = (const float*)d_in[7];
    float* out = (float*)d_out;

    static int done = 0;
    if (!done) {
        cudaFuncSetAttribute(conv_kernel, cudaFuncAttributeMaxDynamicSharedMemorySize,
                             SMEM_WORDS * 4);
        done = 1;
    }

    pool_kernel<<<BB * CC, 128>>>(x);
    gate_kernel<<<1, 64>>>(fc1, fc2, fc2b, alpha_a, out + OUTIMG);
    wform_kernel<<<dim3(144, NK), 256>>>(weight, alpha_w);
    xform_kernel<<<dim3(1, 58, BB), 256>>>(x);
    conv_kernel<<<dim3(28, BB), 256, SMEM_WORDS * 4>>>(bias, out);
}